// round 1
// baseline (speedup 1.0000x reference)
#include <cuda_runtime.h>
#include <cuda_bf16.h>
#include <cstddef>

// y[b][t][c] = d[c] * y[b][t-1][c] + x[b][t][c],  y[b][0][c] = x[b][0][c]
//
// Layout: block = 512 threads = 16 warps (time positions) x 32 lanes (channels).
// Each thread owns R=32 consecutive timesteps of one channel.
// Hierarchy per 512-t macro-tile:
//   1) register-local sequential scan (32 FMAs)
//   2) warp-shuffle scan (width 16) of segment carries as affine maps (a=d^32, b)
//   3) register fix-up: y_k += d^{k+1} * exclusive_prefix, coalesced store
// Block iterates 8 macro-tiles, carrying per-channel prefix P in smem.

#define SEQ   4096
#define NCH   1024
#define CPB   32          // channels per block (= warp width)
#define PWARP 16          // position warps per block
#define RSEG  32          // timesteps per thread per tile
#define TILE_T (PWARP * RSEG)     // 512
#define NTILES (SEQ / TILE_T)     // 8

__global__ __launch_bounds__(512, 2)
void cummulsum_kernel(const float* __restrict__ x,
                      const float* __restrict__ d,
                      float* __restrict__ out)
{
    __shared__ float sb[PWARP][CPB + 1];   // segment carries (pos-major, padded)
    __shared__ float sc[PWARP][CPB + 1];   // inclusive prefixes per position
    __shared__ float sP[CPB];              // per-channel carry across macro-tiles

    const int lane = threadIdx.x & 31;
    const int j    = threadIdx.x >> 5;     // position-warp index 0..15
    const int bx   = blockIdx.x;
    const int b    = bx >> 5;              // batch
    const int c0   = (bx & 31) << 5;       // channel-group base
    const int c    = c0 + lane;

    const float dl = d[c];

    // Phase-2 remap: thread (j,lane) -> (channel = 2j + lane/16, position = lane%16)
    const int p2chan = (j << 1) + (lane >> 4);
    const int p2pos  = lane & 15;
    const float dp2  = d[c0 + p2chan];
    float dR = dp2 * dp2;                  // d^2
    dR *= dR; dR *= dR; dR *= dR; dR *= dR; // d^32

    if (j == 0) sP[lane] = 0.0f;
    __syncthreads();

    size_t base = ((size_t)b * SEQ + (size_t)j * RSEG) * NCH + (size_t)c;
    const float* xp = x + base;
    float*       op = out + base;

    float xs[RSEG];

    for (int m = 0; m < NTILES; m++) {
        // reads of sP happen before S1; this tile's sP write happens after S1
        const float Pl = sP[lane];       // exclusive prefix for phase 3 (j==0)
        const float Pc = sP[p2chan];     // same, for phase-2 pre-combine

        // ---- load R timesteps (coalesced 128B per warp-instr, 32 indep LDGs) ----
        #pragma unroll
        for (int k = 0; k < RSEG; k++)
            xs[k] = xp[(size_t)k * NCH];

        // ---- local sequential scan (zero init; carry handled in phase 2) ----
        float y = 0.0f;
        #pragma unroll
        for (int k = 0; k < RSEG; k++) {
            y = fmaf(dl, y, xs[k]);
            xs[k] = y;
        }
        sb[j][lane] = y;                 // segment carry b_j
        __syncthreads();                 // S1

        // ---- phase 2: 16-wide shuffle scan of (a=d^32, b) per channel ----
        float bb = sb[p2pos][p2chan];
        float ar = dR;
        if (p2pos == 0) bb = fmaf(dR, Pc, bb);   // fold in block carry P
        #pragma unroll
        for (int off = 1; off < 16; off <<= 1) {
            float bu = __shfl_up_sync(0xFFFFFFFFu, bb, off, 16);
            float au = __shfl_up_sync(0xFFFFFFFFu, ar, off, 16);
            if (p2pos >= off) {
                bb = fmaf(ar, bu, bb);   // later(earlier): b = a*b_up + b
                ar *= au;
            }
        }
        sc[p2pos][p2chan] = bb;          // inclusive prefix through position p2pos
        if (p2pos == 15) sP[p2chan] = bb;  // new block carry
        __syncthreads();                 // S2

        // ---- phase 3: fix-up + coalesced store ----
        const float E = (j > 0) ? sc[j - 1][lane] : Pl;  // exclusive prefix
        float pw = dl;
        #pragma unroll
        for (int k = 0; k < RSEG; k++) {
            op[(size_t)k * NCH] = fmaf(pw, E, xs[k]);    // y_k + d^{k+1}*E
            pw *= dl;
        }

        xp += (size_t)TILE_T * NCH;
        op += (size_t)TILE_T * NCH;
    }
}

extern "C" void kernel_launch(void* const* d_in, const int* in_sizes, int n_in,
                              void* d_out, int out_size)
{
    const float* x = (const float*)d_in[0];
    const float* d = (const float*)d_in[1];
    float* out = (float*)d_out;

    const int B = in_sizes[0] / (SEQ * NCH);   // 8
    dim3 grid(B * (NCH / CPB));                // 8 * 32 = 256 blocks
    dim3 block(PWARP * 32);                    // 512 threads
    cummulsum_kernel<<<grid, block>>>(x, d, out);
}

// round 2
// speedup vs baseline: 1.0132x; 1.0132x over previous
#include <cuda_runtime.h>
#include <cuda_bf16.h>
#include <cstddef>

// y[b][t][c] = d[c] * y[b][t-1][c] + x[b][t][c],  y[b][0][c] = x[b][0][c]
//
// Block = 512 threads = 16 warps (time positions) x 32 lanes (channels).
// Each thread owns R=16 consecutive timesteps of one channel.
// Per 256-t macro-tile:
//   1) register-local sequential scan (16 FMAs)
//   2) warp-shuffle scan (width 16) of segment carries as affine maps (a=d^16, b)
//   3) register fix-up with 4 independent power chains + coalesced streaming store
// Double-buffered register prefetch keeps a full tile of LDGs in flight across
// the barrier/scan phases. Block iterates 16 macro-tiles, carry in smem.

#define SEQ   4096
#define NCH   1024
#define CPB   32
#define PWARP 16
#define RSEG  16
#define TILE_T (PWARP * RSEG)     // 256
#define NTILES (SEQ / TILE_T)     // 16

__global__ __launch_bounds__(512, 2)
void cummulsum_kernel(const float* __restrict__ x,
                      const float* __restrict__ d,
                      float* __restrict__ out)
{
    __shared__ float sb[PWARP][CPB + 1];
    __shared__ float sc[PWARP][CPB + 1];
    __shared__ float sP[CPB];

    const int lane = threadIdx.x & 31;
    const int j    = threadIdx.x >> 5;
    const int bx   = blockIdx.x;
    const int b    = bx >> 5;
    const int c0   = (bx & 31) << 5;
    const int c    = c0 + lane;

    const float dl  = d[c];
    const float dl2 = dl * dl;
    const float dl3 = dl2 * dl;
    const float dl4 = dl2 * dl2;

    // Phase-2 remap: thread (j,lane) -> (channel = 2j + lane/16, position = lane%16)
    const int p2chan = (j << 1) + (lane >> 4);
    const int p2pos  = lane & 15;
    const float dp2  = d[c0 + p2chan];
    float dR = dp2 * dp2;                   // d^2
    dR *= dR; dR *= dR; dR *= dR;           // d^16

    if (j == 0) sP[lane] = 0.0f;
    __syncthreads();

    const size_t base   = ((size_t)b * SEQ + (size_t)j * RSEG) * NCH + (size_t)c;
    const size_t tstride = (size_t)TILE_T * NCH;
    const float* xp = x + base;
    float*       op = out + base;

    float A[RSEG], Bf[RSEG];

    // process one tile held in xs[], tile index m
    auto process = [&](float* xs, int m) {
        const float Pl = sP[lane];
        const float Pc = sP[p2chan];

        // local sequential scan (zero init; carry folded in phase 2)
        float y = 0.0f;
        #pragma unroll
        for (int k = 0; k < RSEG; k++) {
            y = fmaf(dl, y, xs[k]);
            xs[k] = y;
        }
        sb[j][lane] = y;
        __syncthreads();                            // S1

        // 16-wide shuffle scan of (a=d^16, b) per channel
        float bb = sb[p2pos][p2chan];
        float ar = dR;
        if (p2pos == 0) bb = fmaf(dR, Pc, bb);
        #pragma unroll
        for (int off = 1; off < 16; off <<= 1) {
            float bu = __shfl_up_sync(0xFFFFFFFFu, bb, off, 16);
            float au = __shfl_up_sync(0xFFFFFFFFu, ar, off, 16);
            if (p2pos >= off) {
                bb = fmaf(ar, bu, bb);
                ar *= au;
            }
        }
        sc[p2pos][p2chan] = bb;
        if (p2pos == 15) sP[p2chan] = bb;
        __syncthreads();                            // S2

        // fix-up + streaming store; 4 independent d^4 power chains
        const float E = (j > 0) ? sc[j - 1][lane] : Pl;
        float f0 = dl  * E;
        float f1 = dl2 * E;
        float f2 = dl3 * E;
        float f3 = dl4 * E;
        float* o = op + (size_t)m * tstride;
        #pragma unroll
        for (int q = 0; q < 4; q++) {
            __stcs(o + (size_t)(4 * q + 0) * NCH, xs[4 * q + 0] + f0);
            __stcs(o + (size_t)(4 * q + 1) * NCH, xs[4 * q + 1] + f1);
            __stcs(o + (size_t)(4 * q + 2) * NCH, xs[4 * q + 2] + f2);
            __stcs(o + (size_t)(4 * q + 3) * NCH, xs[4 * q + 3] + f3);
            f0 *= dl4; f1 *= dl4; f2 *= dl4; f3 *= dl4;
        }
    };

    // prime: load tile 0 into A
    #pragma unroll
    for (int k = 0; k < RSEG; k++)
        A[k] = __ldcs(xp + (size_t)k * NCH);

    for (int m = 0; m < NTILES; m += 2) {
        // prefetch tile m+1 into B before tile m's barrier-heavy phases
        {
            const float* p = xp + (size_t)(m + 1) * tstride;
            #pragma unroll
            for (int k = 0; k < RSEG; k++)
                Bf[k] = __ldcs(p + (size_t)k * NCH);
        }
        process(A, m);

        // prefetch tile m+2 into A
        if (m + 2 < NTILES) {
            const float* p = xp + (size_t)(m + 2) * tstride;
            #pragma unroll
            for (int k = 0; k < RSEG; k++)
                A[k] = __ldcs(p + (size_t)k * NCH);
        }
        process(Bf, m + 1);
    }
}

extern "C" void kernel_launch(void* const* d_in, const int* in_sizes, int n_in,
                              void* d_out, int out_size)
{
    const float* x = (const float*)d_in[0];
    const float* d = (const float*)d_in[1];
    float* out = (float*)d_out;

    const int B = in_sizes[0] / (SEQ * NCH);   // 8
    dim3 grid(B * (NCH / CPB));                // 256 blocks
    dim3 block(PWARP * 32);                    // 512 threads
    cummulsum_kernel<<<grid, block>>>(x, d, out);
}